// round 9
// baseline (speedup 1.0000x reference)
#include <cuda_runtime.h>
#include <cstdint>

// Problem constants (fixed by the dataset): B=2, S=4096, H=1024, I=512, E=8
#define T_TOK   8192
#define H_DIM   1024
#define I_DIM   512
#define E_NUM   8

// GEMM tiling
#define BM      128
#define BN      64
#define BK      32
#define KPADW   36              // BK + 4 pad words -> conflict-free fragment LDS
#define STAGES  3
#define MAXTILES 72
#define PERM_N  (T_TOK + E_NUM * BM)   // 9216 padded permuted rows

// smem word layouts
#define A_W     (BM * KPADW)            // 4608 words
#define B_W     (BN * KPADW)            // 2304 words
#define ST1_W   (A_W + 2 * B_W)         // 9216 words / stage (gemm1: A + G + U)
#define ST2_W   (A_W + B_W)             // 6912 words / stage (gemm2: A + B)
#define SMEM1_BYTES (STAGES * ST1_W * 4 + 512)
#define SMEM2_BYTES (STAGES * ST2_W * 4 + 512)

// ---------------- device scratch (no allocations allowed) ----------------
__device__ int   g_sel[T_TOK];
__device__ float g_rw[T_TOK];
__device__ int   g_counts[E_NUM];
__device__ int   g_fill[E_NUM];
__device__ int   g_expStart[E_NUM];
__device__ int   g_perm[PERM_N];
__device__ int   g_tileExpert[MAXTILES];
__device__ int   g_tileRow[MAXTILES];
__device__ int   g_numTiles;
__device__ __align__(16) float    g_act[(size_t)PERM_N * I_DIM];            // tf32-rounded acts
__device__ __align__(16) uint32_t g_xp [(size_t)PERM_N * H_DIM];            // gathered+rounded tokens
__device__ __align__(16) uint32_t g_wg [(size_t)E_NUM * I_DIM * H_DIM];     // rounded w_gate
__device__ __align__(16) uint32_t g_wu [(size_t)E_NUM * I_DIM * H_DIM];     // rounded w_up
__device__ __align__(16) uint32_t g_wd [(size_t)E_NUM * H_DIM * I_DIM];     // rounded w_down

// ---------------- helpers ----------------
__device__ __forceinline__ uint32_t f2tf32(float x) {
    uint32_t r;
    asm("cvt.rna.tf32.f32 %0, %1;" : "=r"(r) : "f"(x));
    return r;
}
__device__ __forceinline__ uint4 cvt4(float4 v) {
    uint4 u;
    u.x = f2tf32(v.x); u.y = f2tf32(v.y); u.z = f2tf32(v.z); u.w = f2tf32(v.w);
    return u;
}
__device__ __forceinline__ void cpa16(uint32_t saddr, const void* gaddr) {
    asm volatile("cp.async.ca.shared.global [%0], [%1], 16;\n" :: "r"(saddr), "l"(gaddr));
}
__device__ __forceinline__ void cp_commit() { asm volatile("cp.async.commit_group;\n"); }
__device__ __forceinline__ void cp_wait1()  { asm volatile("cp.async.wait_group 1;\n"); }

// D += A*B, m16n8k8 tf32, A row-major, B col-major
__device__ __forceinline__ void mma8(float* acc, const uint32_t* a, const uint32_t* b) {
    asm volatile(
        "mma.sync.aligned.m16n8k8.row.col.f32.tf32.tf32.f32 "
        "{%0,%1,%2,%3}, {%4,%5,%6,%7}, {%8,%9}, {%0,%1,%2,%3};\n"
        : "+f"(acc[0]), "+f"(acc[1]), "+f"(acc[2]), "+f"(acc[3])
        : "r"(a[0]), "r"(a[1]), "r"(a[2]), "r"(a[3]), "r"(b[0]), "r"(b[1]));
}

// ---------------- kernel 0: reset scratch ----------------
__global__ void k_init() {
    int i = blockIdx.x * blockDim.x + threadIdx.x;
    if (i < PERM_N) g_perm[i] = -1;
    if (i < E_NUM) { g_counts[i] = 0; g_fill[i] = 0; }
}

// ---------------- kernel 1: router (1 warp / token) ----------------
__global__ __launch_bounds__(256) void k_router(const float* __restrict__ hs,
                                                const float* __restrict__ gate_w) {
    int warp = (blockIdx.x * 256 + threadIdx.x) >> 5;
    int lane = threadIdx.x & 31;
    if (warp >= T_TOK) return;
    const float* xr = hs + (size_t)warp * H_DIM;

    float xv[32];
#pragma unroll
    for (int i = 0; i < 32; i++) xv[i] = xr[lane + 32 * i];

    float acc[E_NUM];
#pragma unroll
    for (int e = 0; e < E_NUM; e++) {
        const float* w = gate_w + e * H_DIM;
        float s = 0.f;
#pragma unroll
        for (int i = 0; i < 32; i++) s = fmaf(xv[i], w[lane + 32 * i], s);
        acc[e] = s;
    }
#pragma unroll
    for (int e = 0; e < E_NUM; e++) {
#pragma unroll
        for (int o = 16; o > 0; o >>= 1) acc[e] += __shfl_xor_sync(0xffffffffu, acc[e], o);
    }
    int best = 0; float bv = acc[0];
#pragma unroll
    for (int e = 1; e < E_NUM; e++) { if (acc[e] > bv) { bv = acc[e]; best = e; } }

    if (lane == 0) {
        g_sel[warp] = best;
        g_rw[warp]  = 1.f / (1.f + expf(-bv));
        atomicAdd(&g_counts[best], 1);
    }
}

// ---------------- kernel 2: plan (single thread) ----------------
__global__ void k_plan() {
    int rowOff = 0, tiles = 0;
    for (int e = 0; e < E_NUM; e++) {
        g_expStart[e] = rowOff;
        int c  = g_counts[e];
        int nt = (c + BM - 1) / BM;
        for (int t = 0; t < nt; t++) {
            g_tileExpert[tiles] = e;
            g_tileRow[tiles]    = rowOff;
            rowOff += BM;
            tiles++;
        }
    }
    g_numTiles = tiles;
}

// ---------------- kernel 3: scatter tokens into padded per-expert segments ----------------
__global__ void k_scatter() {
    int t = blockIdx.x * blockDim.x + threadIdx.x;
    if (t >= T_TOK) return;
    int e   = g_sel[t];
    int pos = g_expStart[e] + atomicAdd(&g_fill[e], 1);
    g_perm[pos] = t;
}

// ---------------- kernel 3b: pre-round a weight array to tf32 ----------------
__global__ __launch_bounds__(256) void k_roundw(const float4* __restrict__ src,
                                                uint4* __restrict__ dst, int n4) {
    int i = blockIdx.x * blockDim.x + threadIdx.x;
    if (i < n4) dst[i] = cvt4(src[i]);
}

// ---------------- kernel 3c: gather tokens into permuted, tf32-rounded matrix ----------------
__global__ __launch_bounds__(256) void k_gather(const float* __restrict__ hs) {
    int row = blockIdx.x;                       // [0, PERM_N)
    int tok = g_perm[row];
    uint4* dst = (uint4*)&g_xp[(size_t)row * H_DIM] + threadIdx.x;
    if (tok >= 0) {
        float4 v = *((const float4*)(hs + (size_t)tok * H_DIM) + threadIdx.x);
        *dst = cvt4(v);
    } else {
        *dst = make_uint4(0u, 0u, 0u, 0u);
    }
}

// ---------------- kernel 4: fused gate+up GEMM + SiLU (3-stage cp.async pipeline) ----------------
// act = (rw*up) * silu(rw*gate); A rows dense in g_xp (already gathered+rounded).
__global__ __launch_bounds__(256, 2) void k_gemm1() {
    if ((int)blockIdx.x >= g_numTiles) return;
    const int mt = blockIdx.x, nt = blockIdx.y;
    const int e       = g_tileExpert[mt];
    const int rowBase = g_tileRow[mt];
    const int nBase   = nt * BN;
    const size_t wOff = (size_t)e * I_DIM * H_DIM;

    extern __shared__ uint32_t smw[];
    float* sRw = (float*)(smw + STAGES * ST1_W);
    const uint32_t smemBase = (uint32_t)__cvta_generic_to_shared(smw);

    const int tid = threadIdx.x;
    if (tid < BM) {
        int tok = g_perm[rowBase + tid];
        sRw[tid] = (tok >= 0) ? g_rw[tok] : 0.f;
    }

    const int r0 = tid >> 3;            // [0,32)
    const int c4 = (tid & 7) * 4;       // {0,4,...,28}

    // issue one stage's loads (A: 4 chunks, G: 2, U: 2 per thread)
    auto issue = [&](int s, int k0) {
        uint32_t sb = smemBase + (uint32_t)s * (ST1_W * 4);
#pragma unroll
        for (int l = 0; l < 4; l++) {
            int r = r0 + 32 * l;
            cpa16(sb + (uint32_t)(r * KPADW + c4) * 4,
                  &g_xp[(size_t)(rowBase + r) * H_DIM + k0 + c4]);
        }
#pragma unroll
        for (int l = 0; l < 2; l++) {
            int n = r0 + 32 * l;
            uint32_t so = (uint32_t)(n * KPADW + c4) * 4;
            size_t go = wOff + (size_t)(nBase + n) * H_DIM + k0 + c4;
            cpa16(sb + A_W * 4 + so, &g_wg[go]);
            cpa16(sb + (A_W + B_W) * 4 + so, &g_wu[go]);
        }
    };

    const int lane = tid & 31, warp = tid >> 5;
    const int wm = (warp & 3) * 32;
    const int wn = (warp >> 2) * 32;
    const int gID = lane >> 2, tig = lane & 3;

    float accG[2][4][4], accU[2][4][4];
#pragma unroll
    for (int mi = 0; mi < 2; mi++)
#pragma unroll
        for (int ni = 0; ni < 4; ni++)
#pragma unroll
            for (int j = 0; j < 4; j++) { accG[mi][ni][j] = 0.f; accU[mi][ni][j] = 0.f; }

    const int NIT = H_DIM / BK;         // 32
    issue(0, 0);        cp_commit();
    issue(1, BK);       cp_commit();
    cp_wait1();
    __syncthreads();

    for (int it = 0; it < NIT; it++) {
        int cur = it % STAGES;
        if (it + 2 < NIT) issue((it + 2) % STAGES, (it + 2) * BK);
        cp_commit();

        const uint32_t* cA = smw + cur * ST1_W;
        const uint32_t* cG = cA + A_W;
        const uint32_t* cU = cG + B_W;
#pragma unroll
        for (int kk = 0; kk < BK; kk += 8) {
            uint32_t a[2][4];
#pragma unroll
            for (int mi = 0; mi < 2; mi++) {
                const uint32_t* pr = cA + (wm + mi * 16 + gID) * KPADW + kk + tig;
                a[mi][0] = pr[0];
                a[mi][1] = pr[8 * KPADW];
                a[mi][2] = pr[4];
                a[mi][3] = pr[8 * KPADW + 4];
            }
#pragma unroll
            for (int ni = 0; ni < 4; ni++) {
                const uint32_t* pg = cG + (wn + ni * 8 + gID) * KPADW + kk + tig;
                const uint32_t* pu = cU + (wn + ni * 8 + gID) * KPADW + kk + tig;
                uint32_t bg[2] = { pg[0], pg[4] };
                uint32_t bu[2] = { pu[0], pu[4] };
#pragma unroll
                for (int mi = 0; mi < 2; mi++) {
                    mma8(accG[mi][ni], a[mi], bg);
                    mma8(accU[mi][ni], a[mi], bu);
                }
            }
        }
        cp_wait1();
        __syncthreads();
    }

    // epilogue: act = (rw*up) * silu(rw*gate), stored tf32-rounded in permuted layout
#pragma unroll
    for (int mi = 0; mi < 2; mi++) {
#pragma unroll
        for (int ni = 0; ni < 4; ni++) {
#pragma unroll
            for (int half = 0; half < 2; half++) {
                int row = wm + mi * 16 + gID + half * 8;
                int col = nBase + wn + ni * 8 + tig * 2;
                float rw = sRw[row];
                float g0 = rw * accG[mi][ni][half * 2 + 0];
                float g1 = rw * accG[mi][ni][half * 2 + 1];
                float u0 = rw * accU[mi][ni][half * 2 + 0];
                float u1 = rw * accU[mi][ni][half * 2 + 1];
                float a0 = u0 * (g0 / (1.f + __expf(-g0)));
                float a1 = u1 * (g1 / (1.f + __expf(-g1)));
                float2 st;
                st.x = __uint_as_float(f2tf32(a0));
                st.y = __uint_as_float(f2tf32(a1));
                *(float2*)&g_act[(size_t)(rowBase + row) * I_DIM + col] = st;
            }
        }
    }
}

// ---------------- kernel 5: down GEMM + scatter back (3-stage cp.async pipeline) ----------------
__global__ __launch_bounds__(256, 2) void k_gemm2(float* __restrict__ out) {
    if ((int)blockIdx.x >= g_numTiles) return;
    const int mt = blockIdx.x, nt = blockIdx.y;
    const int e       = g_tileExpert[mt];
    const int rowBase = g_tileRow[mt];
    const int nBase   = nt * BN;
    const size_t wOff = (size_t)e * H_DIM * I_DIM;

    extern __shared__ uint32_t smw[];
    int* sTok = (int*)(smw + STAGES * ST2_W);
    const uint32_t smemBase = (uint32_t)__cvta_generic_to_shared(smw);

    const int tid = threadIdx.x;
    if (tid < BM) sTok[tid] = g_perm[rowBase + tid];

    const int r0 = tid >> 3;
    const int c4 = (tid & 7) * 4;

    auto issue = [&](int s, int k0) {
        uint32_t sb = smemBase + (uint32_t)s * (ST2_W * 4);
#pragma unroll
        for (int l = 0; l < 4; l++) {
            int r = r0 + 32 * l;
            cpa16(sb + (uint32_t)(r * KPADW + c4) * 4,
                  &g_act[(size_t)(rowBase + r) * I_DIM + k0 + c4]);
        }
#pragma unroll
        for (int l = 0; l < 2; l++) {
            int n = r0 + 32 * l;
            cpa16(sb + A_W * 4 + (uint32_t)(n * KPADW + c4) * 4,
                  &g_wd[wOff + (size_t)(nBase + n) * I_DIM + k0 + c4]);
        }
    };

    const int lane = tid & 31, warp = tid >> 5;
    const int wm = (warp & 3) * 32, wn = (warp >> 2) * 32;
    const int gID = lane >> 2, tig = lane & 3;

    float acc[2][4][4];
#pragma unroll
    for (int mi = 0; mi < 2; mi++)
#pragma unroll
        for (int ni = 0; ni < 4; ni++)
#pragma unroll
            for (int j = 0; j < 4; j++) acc[mi][ni][j] = 0.f;

    const int NIT = I_DIM / BK;         // 16
    issue(0, 0);        cp_commit();
    issue(1, BK);       cp_commit();
    cp_wait1();
    __syncthreads();

    for (int it = 0; it < NIT; it++) {
        int cur = it % STAGES;
        if (it + 2 < NIT) issue((it + 2) % STAGES, (it + 2) * BK);
        cp_commit();

        const uint32_t* cA = smw + cur * ST2_W;
        const uint32_t* cB = cA + A_W;
#pragma unroll
        for (int kk = 0; kk < BK; kk += 8) {
            uint32_t a[2][4];
#pragma unroll
            for (int mi = 0; mi < 2; mi++) {
                const uint32_t* pr = cA + (wm + mi * 16 + gID) * KPADW + kk + tig;
                a[mi][0] = pr[0];
                a[mi][1] = pr[8 * KPADW];
                a[mi][2] = pr[4];
                a[mi][3] = pr[8 * KPADW + 4];
            }
#pragma unroll
            for (int ni = 0; ni < 4; ni++) {
                const uint32_t* pb = cB + (wn + ni * 8 + gID) * KPADW + kk + tig;
                uint32_t b[2] = { pb[0], pb[4] };
#pragma unroll
                for (int mi = 0; mi < 2; mi++) mma8(acc[mi][ni], a[mi], b);
            }
        }
        cp_wait1();
        __syncthreads();
    }

    // epilogue: scatter back to original token rows (padding rows skipped)
#pragma unroll
    for (int mi = 0; mi < 2; mi++) {
#pragma unroll
        for (int ni = 0; ni < 4; ni++) {
#pragma unroll
            for (int half = 0; half < 2; half++) {
                int row = wm + mi * 16 + gID + half * 8;
                int tok = sTok[row];
                if (tok >= 0) {
                    int col = nBase + wn + ni * 8 + tig * 2;
                    *(float2*)&out[(size_t)tok * H_DIM + col] =
                        make_float2(acc[mi][ni][half * 2 + 0], acc[mi][ni][half * 2 + 1]);
                }
            }
        }
    }
}

// ---------------- launch ----------------
extern "C" void kernel_launch(void* const* d_in, const int* in_sizes, int n_in,
                              void* d_out, int out_size) {
    const float* hs     = (const float*)d_in[0];   // [B,S,H] fp32
    const float* gate_w = (const float*)d_in[1];   // [E,H]
    const float* w_gate = (const float*)d_in[2];   // [E,I,H]
    const float* w_up   = (const float*)d_in[3];   // [E,I,H]
    const float* w_down = (const float*)d_in[4];   // [E,H,I]
    float* out = (float*)d_out;                    // [B,S,H] fp32

    cudaFuncSetAttribute(k_gemm1, cudaFuncAttributeMaxDynamicSharedMemorySize, SMEM1_BYTES);
    cudaFuncSetAttribute(k_gemm2, cudaFuncAttributeMaxDynamicSharedMemorySize, SMEM2_BYTES);

    uint32_t* wg_dst; uint32_t* wu_dst; uint32_t* wd_dst;
    cudaGetSymbolAddress((void**)&wg_dst, g_wg);
    cudaGetSymbolAddress((void**)&wu_dst, g_wu);
    cudaGetSymbolAddress((void**)&wd_dst, g_wd);

    const int n4 = E_NUM * I_DIM * H_DIM / 4;      // 1,048,576 float4 per weight
    k_init<<<(PERM_N + 255) / 256, 256>>>();
    k_roundw<<<n4 / 256, 256>>>((const float4*)w_gate, (uint4*)wg_dst, n4);
    k_roundw<<<n4 / 256, 256>>>((const float4*)w_up,   (uint4*)wu_dst, n4);
    k_roundw<<<n4 / 256, 256>>>((const float4*)w_down, (uint4*)wd_dst, n4);

    k_router<<<T_TOK / 8, 256>>>(hs, gate_w);
    k_plan<<<1, 1>>>();
    k_scatter<<<T_TOK / 256, 256>>>();
    k_gather<<<PERM_N, 256>>>(hs);

    dim3 g1(MAXTILES, I_DIM / BN);   // 72 x 8
    k_gemm1<<<g1, 256, SMEM1_BYTES>>>();

    dim3 g2(MAXTILES, H_DIM / BN);   // 72 x 16
    k_gemm2<<<g2, 256, SMEM2_BYTES>>>(out);
}

// round 12
// speedup vs baseline: 1.4706x; 1.4706x over previous
#include <cuda_runtime.h>
#include <cstdint>

// Problem constants: B=2, S=4096, H=1024, I=512, E=8
#define T_TOK   8192
#define H_DIM   1024
#define I_DIM   512
#define E_NUM   8

// GEMM tiling
#define BM1     64              // gemm1 M-tile (small -> 32 accumulators)
#define BM2     128             // gemm2 M-tile
#define BN      64
#define BK      32
#define KPADW   36              // BK + 4 pad words -> conflict-free fragment LDS
#define MAXT64  144             // ceil(8192/64) + 8 experts padding
#define MAXT128 72
#define PERM_N  (T_TOK + E_NUM * BM2)   // 9216 padded permuted rows (128 granularity)

// ---------------- device scratch (no allocations allowed) ----------------
__device__ int   g_sel[T_TOK];
__device__ float g_rw[T_TOK];
__device__ int   g_counts[E_NUM];
__device__ int   g_fill[E_NUM];
__device__ int   g_expStart[E_NUM];
__device__ int   g_perm[PERM_N];
__device__ int   g_t64Expert[MAXT64];
__device__ int   g_t64Row[MAXT64];
__device__ int   g_t128Expert[MAXT128];
__device__ int   g_t128Row[MAXT128];
__device__ int   g_nt64;
__device__ int   g_nt128;
__device__ __align__(16) float g_act[(size_t)PERM_N * I_DIM];   // permuted intermediate

// ---------------- helpers ----------------
__device__ __forceinline__ uint32_t f2tf32(float x) {
    uint32_t r;
    asm("cvt.rna.tf32.f32 %0, %1;" : "=r"(r) : "f"(x));
    return r;
}
__device__ __forceinline__ uint4 cvt4(float4 v) {
    uint4 u;
    u.x = f2tf32(v.x); u.y = f2tf32(v.y); u.z = f2tf32(v.z); u.w = f2tf32(v.w);
    return u;
}
// D += A*B, m16n8k8 tf32, A row-major, B col-major
__device__ __forceinline__ void mma8(float* acc, const uint32_t* a, const uint32_t* b) {
    asm volatile(
        "mma.sync.aligned.m16n8k8.row.col.f32.tf32.tf32.f32 "
        "{%0,%1,%2,%3}, {%4,%5,%6,%7}, {%8,%9}, {%0,%1,%2,%3};\n"
        : "+f"(acc[0]), "+f"(acc[1]), "+f"(acc[2]), "+f"(acc[3])
        : "r"(a[0]), "r"(a[1]), "r"(a[2]), "r"(a[3]), "r"(b[0]), "r"(b[1]));
}

// ---------------- kernel 1: router (1 warp / token) ----------------
__global__ __launch_bounds__(256) void k_router(const float* __restrict__ hs,
                                                const float* __restrict__ gate_w) {
    int warp = (blockIdx.x * 256 + threadIdx.x) >> 5;
    int lane = threadIdx.x & 31;
    if (warp >= T_TOK) return;
    const float* xr = hs + (size_t)warp * H_DIM;

    float xv[32];
#pragma unroll
    for (int i = 0; i < 32; i++) xv[i] = xr[lane + 32 * i];

    float acc[E_NUM];
#pragma unroll
    for (int e = 0; e < E_NUM; e++) {
        const float* w = gate_w + e * H_DIM;
        float s = 0.f;
#pragma unroll
        for (int i = 0; i < 32; i++) s = fmaf(xv[i], w[lane + 32 * i], s);
        acc[e] = s;
    }
#pragma unroll
    for (int e = 0; e < E_NUM; e++) {
#pragma unroll
        for (int o = 16; o > 0; o >>= 1) acc[e] += __shfl_xor_sync(0xffffffffu, acc[e], o);
    }
    int best = 0; float bv = acc[0];
#pragma unroll
    for (int e = 1; e < E_NUM; e++) { if (acc[e] > bv) { bv = acc[e]; best = e; } }

    if (lane == 0) {
        g_sel[warp] = best;
        g_rw[warp]  = 1.f / (1.f + expf(-bv));
        atomicAdd(&g_counts[best], 1);
    }
}

// ---------------- kernel 2: plan (single thread, builds 64- and 128-row tile tables) ----------------
__global__ void k_plan() {
    int rowOff = 0, t64 = 0, t128 = 0;
    for (int e = 0; e < E_NUM; e++) {
        g_expStart[e] = rowOff;
        int c = g_counts[e];
        int n128 = (c + BM2 - 1) / BM2;
        int n64  = (c + BM1 - 1) / BM1;
        for (int t = 0; t < n128; t++) {
            g_t128Expert[t128] = e;
            g_t128Row[t128]    = rowOff + t * BM2;
            t128++;
        }
        for (int t = 0; t < n64; t++) {
            g_t64Expert[t64] = e;
            g_t64Row[t64]    = rowOff + t * BM1;
            t64++;
        }
        rowOff += n128 * BM2;
    }
    g_nt64  = t64;
    g_nt128 = t128;
}

// ---------------- kernel 3: scatter tokens into padded per-expert segments ----------------
__global__ void k_scatter() {
    int t = blockIdx.x * blockDim.x + threadIdx.x;
    if (t >= T_TOK) return;
    int e   = g_sel[t];
    int pos = g_expStart[e] + atomicAdd(&g_fill[e], 1);
    g_perm[pos] = t;
}

// ---------------- kernel 4: fused gate+up GEMM + SiLU (BM=64, reg prefetch) ----------------
// act = (rw*up) * silu(rw*gate); rw applied in epilogue (exact; padding rows -> rw=0)
__global__ __launch_bounds__(256, 2) void k_gemm1(const float* __restrict__ hs,
                                                  const float* __restrict__ w_gate,
                                                  const float* __restrict__ w_up) {
    if ((int)blockIdx.x >= g_nt64) return;
    const int mt = blockIdx.x, nt = blockIdx.y;
    const int e       = g_t64Expert[mt];
    const int rowBase = g_t64Row[mt];
    const float* Wg = w_gate + (size_t)e * I_DIM * H_DIM;
    const float* Wu = w_up   + (size_t)e * I_DIM * H_DIM;
    const int nBase = nt * BN;

    __shared__ uint32_t sA[BM1][KPADW];
    __shared__ uint32_t sG[BN][KPADW];
    __shared__ uint32_t sU[BN][KPADW];
    __shared__ float    sRw[BM1];

    const int tid = threadIdx.x;
    if (tid < BM1) {
        int tok = g_perm[rowBase + tid];
        sRw[tid] = (tok >= 0) ? g_rw[tok] : 0.f;
    }

    const int r0 = tid >> 3;            // [0,32)
    const int c4 = (tid & 7) * 4;       // {0,4,...,28}

    // per-thread sources: A 2 chunks (gather; padding -> token 0), G/U 2 chunks each
    const float* aP[2];
#pragma unroll
    for (int l = 0; l < 2; l++) {
        int r = r0 + 32 * l;
        int tok = g_perm[rowBase + r];
        if (tok < 0) tok = 0;
        aP[l] = hs + (size_t)tok * H_DIM + c4;
    }
    const float* gP[2]; const float* uP[2];
#pragma unroll
    for (int l = 0; l < 2; l++) {
        int n = r0 + 32 * l;
        gP[l] = Wg + (size_t)(nBase + n) * H_DIM + c4;
        uP[l] = Wu + (size_t)(nBase + n) * H_DIM + c4;
    }

    const int lane = tid & 31, warp = tid >> 5;
    const int wm = (warp & 1) * 32;     // 2 warps along M (64 rows)
    const int wn = (warp >> 1) * 16;    // 4 warps along N (64 cols)
    const int gID = lane >> 2, tig = lane & 3;

    float accG[2][2][4], accU[2][2][4];
#pragma unroll
    for (int mi = 0; mi < 2; mi++)
#pragma unroll
        for (int ni = 0; ni < 2; ni++)
#pragma unroll
            for (int j = 0; j < 4; j++) { accG[mi][ni][j] = 0.f; accU[mi][ni][j] = 0.f; }

    // register prefetch of first slab (6 float4 = 24 regs)
    float4 ra[2], rg[2], ru[2];
#pragma unroll
    for (int l = 0; l < 2; l++) {
        ra[l] = *(const float4*)(aP[l]);
        rg[l] = *(const float4*)(gP[l]);
        ru[l] = *(const float4*)(uP[l]);
    }

    for (int k0 = 0; k0 < H_DIM; k0 += BK) {
#pragma unroll
        for (int l = 0; l < 2; l++) {
            int r = r0 + 32 * l;
            *(uint4*)&sA[r][c4] = cvt4(ra[l]);
            *(uint4*)&sG[r][c4] = cvt4(rg[l]);
            *(uint4*)&sU[r][c4] = cvt4(ru[l]);
        }
        __syncthreads();

        if (k0 + BK < H_DIM) {
#pragma unroll
            for (int l = 0; l < 2; l++) {
                ra[l] = *(const float4*)(aP[l] + k0 + BK);
                rg[l] = *(const float4*)(gP[l] + k0 + BK);
                ru[l] = *(const float4*)(uP[l] + k0 + BK);
            }
        }

#pragma unroll
        for (int kk = 0; kk < BK; kk += 8) {
            uint32_t a[2][4];
#pragma unroll
            for (int mi = 0; mi < 2; mi++) {
                const uint32_t* pr = &sA[wm + mi * 16 + gID][kk + tig];
                a[mi][0] = pr[0];
                a[mi][1] = pr[8 * KPADW];
                a[mi][2] = pr[4];
                a[mi][3] = pr[8 * KPADW + 4];
            }
#pragma unroll
            for (int ni = 0; ni < 2; ni++) {
                int n = wn + ni * 8 + gID;
                uint32_t bg[2] = { sG[n][kk + tig], sG[n][kk + tig + 4] };
                uint32_t bu[2] = { sU[n][kk + tig], sU[n][kk + tig + 4] };
#pragma unroll
                for (int mi = 0; mi < 2; mi++) {
                    mma8(accG[mi][ni], a[mi], bg);
                    mma8(accU[mi][ni], a[mi], bu);
                }
            }
        }
        __syncthreads();
    }

    // epilogue: act = (rw*up) * silu(rw*gate)
#pragma unroll
    for (int mi = 0; mi < 2; mi++) {
#pragma unroll
        for (int ni = 0; ni < 2; ni++) {
#pragma unroll
            for (int half = 0; half < 2; half++) {
                int row = wm + mi * 16 + gID + half * 8;
                int col = nBase + wn + ni * 8 + tig * 2;
                float rw = sRw[row];
                float g0 = rw * accG[mi][ni][half * 2 + 0];
                float g1 = rw * accG[mi][ni][half * 2 + 1];
                float u0 = rw * accU[mi][ni][half * 2 + 0];
                float u1 = rw * accU[mi][ni][half * 2 + 1];
                float a0 = u0 * (g0 / (1.f + __expf(-g0)));
                float a1 = u1 * (g1 / (1.f + __expf(-g1)));
                *(float2*)&g_act[(size_t)(rowBase + row) * I_DIM + col] = make_float2(a0, a1);
            }
        }
    }
}

// ---------------- kernel 5: down GEMM + scatter back (BM=128, reg prefetch) ----------------
__global__ __launch_bounds__(256, 2) void k_gemm2(const float* __restrict__ w_down,
                                                  float* __restrict__ out) {
    if ((int)blockIdx.x >= g_nt128) return;
    const int mt = blockIdx.x, nt = blockIdx.y;
    const int e       = g_t128Expert[mt];
    const int rowBase = g_t128Row[mt];
    const float* Wd = w_down + (size_t)e * H_DIM * I_DIM;
    const int nBase = nt * BN;

    __shared__ uint32_t sA[BM2][KPADW];
    __shared__ uint32_t sB[BN][KPADW];
    __shared__ int sTok[BM2];

    const int tid = threadIdx.x;
    if (tid < BM2) sTok[tid] = g_perm[rowBase + tid];

    const int r0 = tid >> 3;
    const int c4 = (tid & 7) * 4;

    const float* aP[4];
#pragma unroll
    for (int l = 0; l < 4; l++) {
        int r = r0 + 32 * l;
        aP[l] = g_act + (size_t)(rowBase + r) * I_DIM + c4;
    }
    const float* bP[2];
#pragma unroll
    for (int l = 0; l < 2; l++) {
        int n = r0 + 32 * l;
        bP[l] = Wd + (size_t)(nBase + n) * I_DIM + c4;
    }

    const int lane = tid & 31, warp = tid >> 5;
    const int wm = (warp & 3) * 32, wn = (warp >> 2) * 32;
    const int gID = lane >> 2, tig = lane & 3;

    float acc[2][4][4];
#pragma unroll
    for (int mi = 0; mi < 2; mi++)
#pragma unroll
        for (int ni = 0; ni < 4; ni++)
#pragma unroll
            for (int j = 0; j < 4; j++) acc[mi][ni][j] = 0.f;

    // register prefetch of first slab (6 float4 = 24 regs)
    float4 ra[4], rb[2];
#pragma unroll
    for (int l = 0; l < 4; l++) ra[l] = *(const float4*)(aP[l]);
#pragma unroll
    for (int l = 0; l < 2; l++) rb[l] = *(const float4*)(bP[l]);

    for (int k0 = 0; k0 < I_DIM; k0 += BK) {
#pragma unroll
        for (int l = 0; l < 4; l++) {
            int r = r0 + 32 * l;
            *(uint4*)&sA[r][c4] = cvt4(ra[l]);
        }
#pragma unroll
        for (int l = 0; l < 2; l++) {
            int n = r0 + 32 * l;
            *(uint4*)&sB[n][c4] = cvt4(rb[l]);
        }
        __syncthreads();

        if (k0 + BK < I_DIM) {
#pragma unroll
            for (int l = 0; l < 4; l++) ra[l] = *(const float4*)(aP[l] + k0 + BK);
#pragma unroll
            for (int l = 0; l < 2; l++) rb[l] = *(const float4*)(bP[l] + k0 + BK);
        }

#pragma unroll
        for (int kk = 0; kk < BK; kk += 8) {
            uint32_t a[2][4];
#pragma unroll
            for (int mi = 0; mi < 2; mi++) {
                const uint32_t* pr = &sA[wm + mi * 16 + gID][kk + tig];
                a[mi][0] = pr[0];
                a[mi][1] = pr[8 * KPADW];
                a[mi][2] = pr[4];
                a[mi][3] = pr[8 * KPADW + 4];
            }
#pragma unroll
            for (int ni = 0; ni < 4; ni++) {
                int n = wn + ni * 8 + gID;
                uint32_t b[2] = { sB[n][kk + tig], sB[n][kk + tig + 4] };
#pragma unroll
                for (int mi = 0; mi < 2; mi++) mma8(acc[mi][ni], a[mi], b);
            }
        }
        __syncthreads();
    }

    // epilogue: scatter back to original token rows (padding rows skipped)
#pragma unroll
    for (int mi = 0; mi < 2; mi++) {
#pragma unroll
        for (int ni = 0; ni < 4; ni++) {
#pragma unroll
            for (int half = 0; half < 2; half++) {
                int row = wm + mi * 16 + gID + half * 8;
                int tok = sTok[row];
                if (tok >= 0) {
                    int col = nBase + wn + ni * 8 + tig * 2;
                    *(float2*)&out[(size_t)tok * H_DIM + col] =
                        make_float2(acc[mi][ni][half * 2 + 0], acc[mi][ni][half * 2 + 1]);
                }
            }
        }
    }
}

// ---------------- launch ----------------
extern "C" void kernel_launch(void* const* d_in, const int* in_sizes, int n_in,
                              void* d_out, int out_size) {
    const float* hs     = (const float*)d_in[0];   // [B,S,H] fp32
    const float* gate_w = (const float*)d_in[1];   // [E,H]
    const float* w_gate = (const float*)d_in[2];   // [E,I,H]
    const float* w_up   = (const float*)d_in[3];   // [E,I,H]
    const float* w_down = (const float*)d_in[4];   // [E,H,I]
    float* out = (float*)d_out;                    // [B,S,H] fp32

    // reset scratch via async memsets (not kernel launches -> keeps gemm1 at launch index 3)
    void *pPerm, *pCnt, *pFill;
    cudaGetSymbolAddress(&pPerm, g_perm);
    cudaGetSymbolAddress(&pCnt,  g_counts);
    cudaGetSymbolAddress(&pFill, g_fill);
    cudaMemsetAsync(pPerm, 0xFF, PERM_N * sizeof(int));   // -1
    cudaMemsetAsync(pCnt,  0, E_NUM * sizeof(int));
    cudaMemsetAsync(pFill, 0, E_NUM * sizeof(int));

    k_router<<<T_TOK / 8, 256>>>(hs, gate_w);      // launch 0
    k_plan<<<1, 1>>>();                            // launch 1
    k_scatter<<<T_TOK / 256, 256>>>();             // launch 2

    dim3 g1(MAXT64, I_DIM / BN);                   // 144 x 8   (launch 3)
    k_gemm1<<<g1, 256>>>(hs, w_gate, w_up);

    dim3 g2(MAXT128, H_DIM / BN);                  // 72 x 16   (launch 4)
    k_gemm2<<<g2, 256>>>(w_down, out);
}